// round 10
// baseline (speedup 1.0000x reference)
#include <cuda_runtime.h>
#include <cuda_bf16.h>
#include <math.h>
#include <stdint.h>

#define IN_DIM   256
#define OUT_DIM  256
#define BATCH    4096
#define NROWS    12
#define KSEG     (IN_DIM * NROWS)      // 3072 k per segment
#define KROW     (3 * KSEG)            // 9216 bytes per row (A and B, 3 segments)
#define KC       256                   // k (bytes) per chunk
#define NCH      (KROW / KC)           // 36
#define NCH0     (KSEG / KC)           // 12 chunks in segment 0 (a1*w1)

// Scratch (static __device__ — no allocation).
__device__ int8_t g_A[(size_t)BATCH * KROW];     // [b][a1|a1|a2]  ~37.7 MB
__device__ int8_t g_B[(size_t)OUT_DIM * KROW];   // [o][w1|w2|w1]  ~2.4 MB
__device__ float  g_SW[OUT_DIM];                 // per-o weight scale

// ===========================================================================
// Kernel 1: A digits — dense 12-wide basis/silu per (b,i), X=round(A*2^14),
// a1=(X+64)>>7, a2=X-128*a1. Smem-staged, coalesced uint4 stores.
// ===========================================================================
__global__ void __launch_bounds__(256) prep_a(const float* __restrict__ x) {
    __shared__ uint32_t st[1536];                 // a1 image (768 u32) | a2 image
    int b = blockIdx.x;
    int i = threadIdx.x;
    float xv = x[(size_t)b * IN_DIM + i];
    float t8 = xv * 8.0f;
    float fl = floorf(t8);
    float u  = t8 - fl;
    int k0l = min(max((int)fl, 0), 7);
    const float inv6 = 1.0f / 6.0f;
    float u2 = u * u, u3 = u2 * u;
    float omu = 1.0f - u;
    float d[NROWS];
#pragma unroll
    for (int kk = 0; kk < NROWS; kk++) d[kk] = 0.0f;
    d[k0l + 0] = omu * omu * omu * inv6;
    d[k0l + 1] = (3.0f * u3 - 6.0f * u2 + 4.0f) * inv6;
    d[k0l + 2] = (-3.0f * u3 + 3.0f * u2 + 3.0f * u + 1.0f) * inv6;
    d[k0l + 3] = u3 * inv6;
    d[11]      = xv / (1.0f + expf(-xv));         // silu, >= 0 for x in [0,1)

    int a1[NROWS], a2[NROWS];
#pragma unroll
    for (int kk = 0; kk < NROWS; kk++) {
        int X = __float2int_rn(d[kk] * 16384.0f); // [0, ~12000]
        a1[kk] = (X + 64) >> 7;                   // [0, 95]
        a2[kk] = X - (a1[kk] << 7);               // [-64, 63]
    }
#pragma unroll
    for (int j = 0; j < 3; j++) {
        uint32_t p1 = ((uint32_t)(uint8_t)a1[4*j])          |
                      ((uint32_t)(uint8_t)a1[4*j+1] << 8)   |
                      ((uint32_t)(uint8_t)a1[4*j+2] << 16)  |
                      ((uint32_t)(uint8_t)a1[4*j+3] << 24);
        uint32_t p2 = ((uint32_t)(uint8_t)a2[4*j])          |
                      ((uint32_t)(uint8_t)a2[4*j+1] << 8)   |
                      ((uint32_t)(uint8_t)a2[4*j+2] << 16)  |
                      ((uint32_t)(uint8_t)a2[4*j+3] << 24);
        st[i * 3 + j]       = p1;
        st[768 + i * 3 + j] = p2;
    }
    __syncthreads();

    const uint4* s4 = reinterpret_cast<const uint4*>(st);   // 192 a1 | 192 a2
    uint4* g4 = reinterpret_cast<uint4*>(g_A) + (size_t)b * 576;
#pragma unroll
    for (int p = 0; p < 3; p++) {                 // dst segs: a1, a1, a2
        int j = p * 256 + i;
        if (j < 576) {
            int src = (j >= 384) ? (192 + (j - 384)) : (j % 192);
            g4[j] = s4[src];
        }
    }
}

// ===========================================================================
// Kernel 2: B digits — W[i][kk][o] = sc*cp (row 11 = sc); per-o max-abs scale;
// Y = round(W/SW * 8192); w1/w2 digits; segs w1|w2|w1.
// ===========================================================================
__global__ void __launch_bounds__(256) prep_b(const float* __restrict__ cp,
                                              const float* __restrict__ sc) {
    __shared__ float rmax[256];
    __shared__ uint32_t st[1536];                 // w1 image | w2 image
    int o = blockIdx.x;
    int i = threadIdx.x;
    float s = sc[i * OUT_DIM + o];
    const float* cpp = cp + (size_t)(i * OUT_DIM + o) * 19;
    float w[NROWS];
    float mx = 0.0f;
#pragma unroll
    for (int kk = 0; kk < NROWS; kk++) {
        w[kk] = (kk < 11) ? s * cpp[kk + 8] : s;
        mx = fmaxf(mx, fabsf(w[kk]));
    }
    rmax[i] = mx;
    __syncthreads();
#pragma unroll
    for (int r = 128; r > 0; r >>= 1) {
        if (i < r) rmax[i] = fmaxf(rmax[i], rmax[i + r]);
        __syncthreads();
    }
    float SW = fmaxf(rmax[0], 1e-30f);
    if (i == 0) g_SW[o] = SW;
    float q = 8192.0f / SW;

    int w1[NROWS], w2[NROWS];
#pragma unroll
    for (int kk = 0; kk < NROWS; kk++) {
        int Y = __float2int_rn(w[kk] * q);
        Y = min(max(Y, -8192), 8192);
        int t = (Y + 8192 + 64) >> 7;             // [0,128]
        w1[kk] = t - 64;                          // [-64,64]
        w2[kk] = Y - (w1[kk] << 7);               // [-64,63]
    }
#pragma unroll
    for (int j = 0; j < 3; j++) {
        uint32_t p1 = ((uint32_t)(uint8_t)w1[4*j])          |
                      ((uint32_t)(uint8_t)w1[4*j+1] << 8)   |
                      ((uint32_t)(uint8_t)w1[4*j+2] << 16)  |
                      ((uint32_t)(uint8_t)w1[4*j+3] << 24);
        uint32_t p2 = ((uint32_t)(uint8_t)w2[4*j])          |
                      ((uint32_t)(uint8_t)w2[4*j+1] << 8)   |
                      ((uint32_t)(uint8_t)w2[4*j+2] << 16)  |
                      ((uint32_t)(uint8_t)w2[4*j+3] << 24);
        st[i * 3 + j]       = p1;
        st[768 + i * 3 + j] = p2;
    }
    __syncthreads();
    const uint4* s4 = reinterpret_cast<const uint4*>(st);   // 192 w1 | 192 w2
    uint4* g4 = reinterpret_cast<uint4*>(g_B) + (size_t)o * 576;
#pragma unroll
    for (int p = 0; p < 3; p++) {                 // dst segs: w1, w2, w1
        int j = p * 256 + i;
        if (j < 576) {
            int src = (j < 192) ? j : ((j < 384) ? (192 + (j - 192)) : (j - 384));
            g4[j] = s4[src];
        }
    }
}

// ===========================================================================
// PTX helpers (sm_80-class: cp.async, ldmatrix, imma — no tcgen05)
// ===========================================================================
__device__ __forceinline__ uint32_t smem_u32(const void* p) {
    uint32_t a;
    asm("{ .reg .u64 t; cvta.to.shared.u64 t, %1; cvt.u32.u64 %0, t; }"
        : "=r"(a) : "l"(p));
    return a;
}
__device__ __forceinline__ void cp16(uint32_t dst, const void* src) {
    asm volatile("cp.async.cg.shared.global [%0], [%1], 16;"
                 :: "r"(dst), "l"(src) : "memory");
}
__device__ __forceinline__ void cp_commit() {
    asm volatile("cp.async.commit_group;" ::: "memory");
}
template <int N>
__device__ __forceinline__ void cp_wait() {
    asm volatile("cp.async.wait_group %0;" :: "n"(N) : "memory");
}
__device__ __forceinline__ void ldm_x4(uint32_t* r, uint32_t addr) {
    asm volatile("ldmatrix.sync.aligned.m8n8.x4.shared.b16 {%0,%1,%2,%3}, [%4];"
                 : "=r"(r[0]), "=r"(r[1]), "=r"(r[2]), "=r"(r[3]) : "r"(addr));
}
__device__ __forceinline__ void imma16832(int32_t* d, const uint32_t* a,
                                          const uint32_t* b) {
    asm volatile(
        "mma.sync.aligned.m16n8k32.row.col.s32.s8.s8.s32 "
        "{%0,%1,%2,%3}, {%4,%5,%6,%7}, {%8,%9}, {%0,%1,%2,%3};"
        : "+r"(d[0]), "+r"(d[1]), "+r"(d[2]), "+r"(d[3])
        : "r"(a[0]), "r"(a[1]), "r"(a[2]), "r"(a[3]), "r"(b[0]), "r"(b[1]));
}

// ===========================================================================
// Kernel 3: IMMA GEMM. out[4096,256] = dequant(Aq · Bq^T).
// CTA: M=128, N=64. grid = 32 btiles x 4 ntiles = 128 CTAs, 256 threads.
// Warps 4(M)x2(N); warp tile 32x32. KC=256 bytes (8 k-steps of 32), 36 chunks,
// 3-stage cp.async, ONE sync/chunk. Dual s32 accumulators:
//   chunks 0..11  (a1*w1, scale 16384) -> acc0
//   chunks 12..35 (a1*w2 + a2*w1, scale 128) -> acc1
// out = SW[o] * (acc0*2^-13 + acc1*2^-20).
// Smem rows 272B stride (mod 128 = 16 -> conflict-free ldmatrix).
// s8 m16n8k32 fragments are byte-identical to b16 m16n8k16 -> same ldmatrix map.
// ===========================================================================
#define ROWB  272                       // bytes per padded smem row (256 data)
#define ASTG  (128 * ROWB)              // 34816
#define BSTG  (64 * ROWB)               // 17408
#define STG_B (ASTG + BSTG)             // 52224 per stage
#define SMTOT (3 * STG_B)               // 156672

__global__ void __launch_bounds__(256) kan_mma(float* __restrict__ out) {
    extern __shared__ char smem[];
    uint32_t sbase = smem_u32(smem);
    uint32_t sA[3], sB[3];
#pragma unroll
    for (int s = 0; s < 3; s++) {
        sA[s] = sbase + s * STG_B;
        sB[s] = sbase + s * STG_B + ASTG;
    }

    int tid  = threadIdx.x;
    int wid  = tid >> 5;
    int lane = tid & 31;
    int btile = blockIdx.x >> 2;          // 0..31
    int ntile = blockIdx.x & 3;           // 0..3
    int warp_m = wid >> 1;                // 0..3
    int warp_n = wid & 1;                 // 0..1

    // ---- cp.async per-thread mapping (A: 8 ops, B: 4 ops per chunk) ----
    int u      = tid & 15;                // 16B unit in 256B row
    int row0   = tid >> 4;                // 0..15
    const int8_t* gA[8];
    uint32_t dA[8];
#pragma unroll
    for (int j = 0; j < 8; j++) {
        int r = row0 + 16 * j;
        gA[j] = g_A + (size_t)(btile * 128 + r) * KROW + u * 16;
        dA[j] = r * ROWB + u * 16;
    }
    const int8_t* gB[4];
    uint32_t dB[4];
#pragma unroll
    for (int j = 0; j < 4; j++) {
        int r = row0 + 16 * j;
        gB[j] = g_B + (size_t)(ntile * 64 + r) * KROW + u * 16;
        dB[j] = r * ROWB + u * 16;
    }

    // ---- ldmatrix per-lane base offsets (same geometry as bf16 path) ----
    uint32_t a_off[2];
#pragma unroll
    for (int mt = 0; mt < 2; mt++) {
        int r = warp_m * 32 + mt * 16 + (lane & 7) + 8 * ((lane >> 3) & 1);
        a_off[mt] = r * ROWB + (lane >> 4) * 16;
    }
    uint32_t b_off[2];
#pragma unroll
    for (int np = 0; np < 2; np++) {
        int r = warp_n * 32 + np * 16 + ((lane >> 4) & 1) * 8 + (lane & 7);
        b_off[np] = r * ROWB + ((lane >> 3) & 1) * 16;
    }

    int32_t acc0[2][4][4], acc1[2][4][4];
#pragma unroll
    for (int mt = 0; mt < 2; mt++)
#pragma unroll
        for (int nt = 0; nt < 4; nt++)
#pragma unroll
            for (int q = 0; q < 4; q++) { acc0[mt][nt][q] = 0; acc1[mt][nt][q] = 0; }

#define ISSUE(c, s) do {                                                        \
        int _off = (c) * KC;                                                    \
        _Pragma("unroll")                                                       \
        for (int j = 0; j < 8; j++)                                             \
            cp16(sA[s] + dA[j], gA[j] + _off);                                  \
        _Pragma("unroll")                                                       \
        for (int j = 0; j < 4; j++)                                             \
            cp16(sB[s] + dB[j], gB[j] + _off);                                  \
        cp_commit();                                                            \
    } while (0)

#define CHUNK_BODY(c, ACC) do {                                                 \
        int _s = (c) % 3;                                                       \
        if ((c) + 1 < NCH) cp_wait<1>(); else cp_wait<0>();                     \
        __syncthreads();                                                        \
        if ((c) + 2 < NCH) ISSUE((c) + 2, ((c) + 2) % 3);                       \
        _Pragma("unroll")                                                       \
        for (int ks = 0; ks < 8; ks++) {                                        \
            uint32_t kb = ks * 32;                                              \
            uint32_t afr[2][4], bfr[2][4];                                      \
            _Pragma("unroll")                                                   \
            for (int mt = 0; mt < 2; mt++)                                      \
                ldm_x4(afr[mt], sA[_s] + a_off[mt] + kb);                       \
            _Pragma("unroll")                                                   \
            for (int np = 0; np < 2; np++)                                      \
                ldm_x4(bfr[np], sB[_s] + b_off[np] + kb);                       \
            _Pragma("unroll")                                                   \
            for (int mt = 0; mt < 2; mt++) {                                    \
                _Pragma("unroll")                                               \
                for (int nt = 0; nt < 4; nt++) {                                \
                    uint32_t bb[2] = { bfr[nt >> 1][(nt & 1) * 2 + 0],          \
                                       bfr[nt >> 1][(nt & 1) * 2 + 1] };        \
                    imma16832(ACC[mt][nt], afr[mt], bb);                        \
                }                                                               \
            }                                                                   \
        }                                                                       \
    } while (0)

    // prologue: 2 chunks in flight
    ISSUE(0, 0);
    ISSUE(1, 1);

    for (int c = 0; c < NCH0; c++)      CHUNK_BODY(c, acc0);   // a1*w1
    for (int c = NCH0; c < NCH; c++)    CHUNK_BODY(c, acc1);   // cross terms

    // ---- epilogue: out = SW[o] * (acc0*2^-13 + acc1*2^-20) ----
    const float C0 = 1.0f / 8192.0f;
    const float C1 = 1.0f / 1048576.0f;
    int mg = btile * 128 + warp_m * 32 + (lane >> 2);
    int ng = ntile * 64 + warp_n * 32 + (lane & 3) * 2;
#pragma unroll
    for (int mt = 0; mt < 2; mt++) {
#pragma unroll
        for (int nt = 0; nt < 4; nt++) {
            int m0 = mg + mt * 16;
            int n0 = ng + nt * 8;
            float sw0 = g_SW[n0];
            float sw1 = g_SW[n0 + 1];
            float2 v0 = make_float2(
                sw0 * ((float)acc0[mt][nt][0] * C0 + (float)acc1[mt][nt][0] * C1),
                sw1 * ((float)acc0[mt][nt][1] * C0 + (float)acc1[mt][nt][1] * C1));
            float2 v1 = make_float2(
                sw0 * ((float)acc0[mt][nt][2] * C0 + (float)acc1[mt][nt][2] * C1),
                sw1 * ((float)acc0[mt][nt][3] * C0 + (float)acc1[mt][nt][3] * C1));
            *reinterpret_cast<float2*>(out + (size_t)m0 * OUT_DIM + n0) = v0;
            *reinterpret_cast<float2*>(out + (size_t)(m0 + 8) * OUT_DIM + n0) = v1;
        }
    }
#undef CHUNK_BODY
#undef ISSUE
}

// ---------------------------------------------------------------------------
extern "C" void kernel_launch(void* const* d_in, const int* in_sizes, int n_in,
                              void* d_out, int out_size) {
    const float* x  = (const float*)d_in[0];   // [4096, 256]
    const float* cp = (const float*)d_in[1];   // [256, 256, 19]
    const float* sc = (const float*)d_in[2];   // [256, 256]
    float* out = (float*)d_out;                // [4096, 256]

    cudaFuncSetAttribute(kan_mma, cudaFuncAttributeMaxDynamicSharedMemorySize,
                         SMTOT);

    prep_a<<<BATCH,   IN_DIM>>>(x);
    prep_b<<<OUT_DIM, IN_DIM>>>(cp, sc);
    kan_mma<<<128, 256, SMTOT>>>(out);
}

// round 12
// speedup vs baseline: 1.3791x; 1.3791x over previous
#include <cuda_runtime.h>
#include <cuda_bf16.h>
#include <math.h>
#include <stdint.h>

#define IN_DIM   256
#define OUT_DIM  256
#define BATCH    4096
#define NROWS    12
#define KSEG     (IN_DIM * NROWS)      // 3072 dense K per term
#define KA       (2 * KSEG)            // A_cat row: hi | lo           = 6144
#define KB       (3 * KSEG)            // B_cat row: Whi | Wlo | Whi   = 9216
#define KC       128                   // K per chunk
#define NCH      (KB / KC)             // 72
#define CSEG     (KSEG / KC)           // 24

// Scratch (static __device__ — no allocation).
__device__ __nv_bfloat16 g_A[(size_t)BATCH * KA];    // ~50 MB (L2-resident)
__device__ __nv_bfloat16 g_B[(size_t)OUT_DIM * KB];  // ~4.7 MB

// ===========================================================================
// Kernel 1: A_cat — dense 12-wide basis/silu per (b,i), split hi|lo bf16.
// Smem-staged: pack 12+12 bf16 into u32 pairs, then coalesced uint4 stores.
// ===========================================================================
__global__ void __launch_bounds__(256) prep_a(const float* __restrict__ x) {
    __shared__ uint32_t st[3072];                 // 12 KB row image for batch b
    int b = blockIdx.x;
    int i = threadIdx.x;
    float xv = x[(size_t)b * IN_DIM + i];
    float t8 = xv * 8.0f;
    float fl = floorf(t8);
    float u  = t8 - fl;
    int k0l = min(max((int)fl, 0), 7);
    const float inv6 = 1.0f / 6.0f;
    float u2 = u * u, u3 = u2 * u;
    float omu = 1.0f - u;
    float d[NROWS];
#pragma unroll
    for (int kk = 0; kk < NROWS; kk++) d[kk] = 0.0f;
    d[k0l + 0] = omu * omu * omu * inv6;
    d[k0l + 1] = (3.0f * u3 - 6.0f * u2 + 4.0f) * inv6;
    d[k0l + 2] = (-3.0f * u3 + 3.0f * u2 + 3.0f * u + 1.0f) * inv6;
    d[k0l + 3] = u3 * inv6;
    d[11]      = xv / (1.0f + expf(-xv));         // silu

    unsigned short hb[NROWS], lb[NROWS];
#pragma unroll
    for (int kk = 0; kk < NROWS; kk++) {
        float v = d[kk];
        __nv_bfloat16 h = __float2bfloat16(v);
        float lo = v - __bfloat162float(h);
        __nv_bfloat16 l = __float2bfloat16(lo);
        hb[kk] = *reinterpret_cast<unsigned short*>(&h);
        lb[kk] = *reinterpret_cast<unsigned short*>(&l);
    }
#pragma unroll
    for (int j = 0; j < 6; j++) {
        st[i * 6 + j]        = (uint32_t)hb[2 * j] | ((uint32_t)hb[2 * j + 1] << 16);
        st[1536 + i * 6 + j] = (uint32_t)lb[2 * j] | ((uint32_t)lb[2 * j + 1] << 16);
    }
    __syncthreads();

    const uint4* s4 = reinterpret_cast<const uint4*>(st);
    uint4* g4 = reinterpret_cast<uint4*>(g_A) + (size_t)b * 768;
#pragma unroll
    for (int p = 0; p < 3; p++)
        g4[p * 256 + i] = s4[p * 256 + i];
}

// ===========================================================================
// Kernel 2: B_cat — W[i][kk][o] = sc*cp (row 11 = sc), split Whi|Wlo|Whi.
// ===========================================================================
__global__ void prep_b(const float* __restrict__ cp, const float* __restrict__ sc) {
    int o = blockIdx.x;
    int i = threadIdx.x;
    float s = sc[i * OUT_DIM + o];
    const float* cpp = cp + (size_t)(i * OUT_DIM + o) * 19;
    __nv_bfloat16* pb = g_B + (size_t)o * KB + i * NROWS;
#pragma unroll
    for (int kk = 0; kk < NROWS; kk++) {
        float w = (kk < 11) ? s * cpp[kk + 8] : s;
        __nv_bfloat16 h = __float2bfloat16(w);
        float lo = w - __bfloat162float(h);
        pb[kk]            = h;
        pb[KSEG + kk]     = __float2bfloat16(lo);
        pb[2 * KSEG + kk] = h;
    }
}

// ===========================================================================
// PTX helpers (sm_80-class only: cp.async, ldmatrix, mma.sync — no tcgen05)
// ===========================================================================
__device__ __forceinline__ uint32_t smem_u32(const void* p) {
    uint32_t a;
    asm("{ .reg .u64 t; cvta.to.shared.u64 t, %1; cvt.u32.u64 %0, t; }"
        : "=r"(a) : "l"(p));
    return a;
}
__device__ __forceinline__ void cp16(uint32_t dst, const void* src) {
    asm volatile("cp.async.cg.shared.global [%0], [%1], 16;"
                 :: "r"(dst), "l"(src) : "memory");
}
__device__ __forceinline__ void cp_commit() {
    asm volatile("cp.async.commit_group;" ::: "memory");
}
template <int N>
__device__ __forceinline__ void cp_wait() {
    asm volatile("cp.async.wait_group %0;" :: "n"(N) : "memory");
}
__device__ __forceinline__ void ldm_x4(uint32_t* r, uint32_t addr) {
    asm volatile("ldmatrix.sync.aligned.m8n8.x4.shared.b16 {%0,%1,%2,%3}, [%4];"
                 : "=r"(r[0]), "=r"(r[1]), "=r"(r[2]), "=r"(r[3]) : "r"(addr));
}
__device__ __forceinline__ void mma16816(float* d, const uint32_t* a,
                                         const uint32_t* b) {
    asm volatile(
        "mma.sync.aligned.m16n8k16.row.col.f32.bf16.bf16.f32 "
        "{%0,%1,%2,%3}, {%4,%5,%6,%7}, {%8,%9}, {%0,%1,%2,%3};"
        : "+f"(d[0]), "+f"(d[1]), "+f"(d[2]), "+f"(d[3])
        : "r"(a[0]), "r"(a[1]), "r"(a[2]), "r"(a[3]), "r"(b[0]), "r"(b[1]));
}

// ===========================================================================
// Kernel 3: HMMA GEMM. out[4096,256] = A_cat · B_cat^T.
// CTA: M=64, N=64. grid = 64 btiles x 4 ntiles = 256 CTAs (2 per SM),
// 256 threads. Warps 2(M)x4(N); warp tile 32x16 (2 mt x 2 nt).
// KC=128 (8 k-steps per barrier), 3-stage cp.async pipeline, ONE sync/chunk.
// Smem rows 272B stride (r*272 mod 128 = r*16 -> conflict-free ldmatrix).
// ===========================================================================
#define ROWB  272                       // bytes per padded smem row (256 data)
#define ASTG  (64 * ROWB)               // 17408
#define BSTG  (64 * ROWB)               // 17408
#define STG_B (ASTG + BSTG)             // 34816 per stage
#define SMTOT (3 * STG_B)               // 104448 (2 CTAs -> 204 KB < 227 KB)

__global__ void __launch_bounds__(256) kan_mma(float* __restrict__ out) {
    extern __shared__ char smem[];
    uint32_t sbase = smem_u32(smem);
    uint32_t sA[3], sB[3];
#pragma unroll
    for (int s = 0; s < 3; s++) {
        sA[s] = sbase + s * STG_B;
        sB[s] = sbase + s * STG_B + ASTG;
    }

    int tid  = threadIdx.x;
    int wid  = tid >> 5;
    int lane = tid & 31;
    int btile = blockIdx.x >> 2;          // 0..63
    int ntile = blockIdx.x & 3;           // 0..3
    int warp_m = wid >> 2;                // 0..1
    int warp_n = wid & 3;                 // 0..3

    // ---- cp.async per-thread mapping (A: 4 ops, B: 4 ops per chunk) ----
    int u      = tid & 15;                // 16B unit in 256B row
    int row0   = tid >> 4;                // 0..15
    const __nv_bfloat16* gA[4];
    uint32_t dA[4];
#pragma unroll
    for (int j = 0; j < 4; j++) {
        int r = row0 + 16 * j;
        gA[j] = g_A + (size_t)(btile * 64 + r) * KA + u * 8;
        dA[j] = r * ROWB + u * 16;
    }
    const __nv_bfloat16* gB[4];
    uint32_t dB[4];
#pragma unroll
    for (int j = 0; j < 4; j++) {
        int r = row0 + 16 * j;
        gB[j] = g_B + (size_t)(ntile * 64 + r) * KB + u * 8;
        dB[j] = r * ROWB + u * 16;
    }

    // ---- ldmatrix per-lane base offsets ----
    // A x4 per mt: row = warp_m*32 + mt*16 + (lane&7) + 8*((lane>>3)&1), khalf=(lane>>4)
    uint32_t a_off[2];
#pragma unroll
    for (int mt = 0; mt < 2; mt++) {
        int r = warp_m * 32 + mt * 16 + (lane & 7) + 8 * ((lane >> 3) & 1);
        a_off[mt] = r * ROWB + (lane >> 4) * 16;
    }
    // B x4 (covers warp's 16 n-rows, both k-halves):
    // row = warp_n*16 + 8*((lane>>4)&1) + (lane&7), khalf = (lane>>3)&1
    // -> bfr = {n8t0k0, n8t0k1, n8t1k0, n8t1k1}
    uint32_t b_off;
    {
        int r = warp_n * 16 + ((lane >> 4) & 1) * 8 + (lane & 7);
        b_off = r * ROWB + ((lane >> 3) & 1) * 16;
    }

    float acc[2][2][4];
#pragma unroll
    for (int mt = 0; mt < 2; mt++)
#pragma unroll
        for (int nt = 0; nt < 2; nt++)
#pragma unroll
            for (int q = 0; q < 4; q++) acc[mt][nt][q] = 0.0f;

#define ISSUE(c, s) do {                                                        \
        int _c = (c);                                                           \
        int _seg = _c / CSEG;                                                   \
        int _aoff = ((_seg == 2) ? KSEG : 0) + (_c - _seg * CSEG) * KC;         \
        int _boff = _c * KC;                                                    \
        _Pragma("unroll")                                                       \
        for (int j = 0; j < 4; j++)                                             \
            cp16(sA[s] + dA[j], gA[j] + _aoff);                                 \
        _Pragma("unroll")                                                       \
        for (int j = 0; j < 4; j++)                                             \
            cp16(sB[s] + dB[j], gB[j] + _boff);                                 \
        cp_commit();                                                            \
    } while (0)

    // prologue: 2 chunks in flight
    ISSUE(0, 0);
    ISSUE(1, 1);

    for (int c = 0; c < NCH; c++) {
        int s = c % 3;
        if (c + 1 < NCH) cp_wait<1>(); else cp_wait<0>();
        __syncthreads();

        if (c + 2 < NCH) ISSUE(c + 2, (c + 2) % 3);   // stage freed at iter c-1

#pragma unroll
        for (int ks = 0; ks < 8; ks++) {
            uint32_t kb = ks * 32;
            uint32_t afr[2][4], bfr[4];
#pragma unroll
            for (int mt = 0; mt < 2; mt++)
                ldm_x4(afr[mt], sA[s] + a_off[mt] + kb);
            ldm_x4(bfr, sB[s] + b_off + kb);
#pragma unroll
            for (int mt = 0; mt < 2; mt++) {
#pragma unroll
                for (int nt = 0; nt < 2; nt++) {
                    uint32_t bb[2] = { bfr[nt * 2 + 0], bfr[nt * 2 + 1] };
                    mma16816(acc[mt][nt], afr[mt], bb);
                }
            }
        }
    }

    // ---- epilogue ----
    int mg = btile * 64 + warp_m * 32 + (lane >> 2);
    int ng = ntile * 64 + warp_n * 16 + (lane & 3) * 2;
#pragma unroll
    for (int mt = 0; mt < 2; mt++) {
#pragma unroll
        for (int nt = 0; nt < 2; nt++) {
            int m0 = mg + mt * 16;
            int n0 = ng + nt * 8;
            float2 v0 = make_float2(acc[mt][nt][0], acc[mt][nt][1]);
            float2 v1 = make_float2(acc[mt][nt][2], acc[mt][nt][3]);
            *reinterpret_cast<float2*>(out + (size_t)m0 * OUT_DIM + n0) = v0;
            *reinterpret_cast<float2*>(out + (size_t)(m0 + 8) * OUT_DIM + n0) = v1;
        }
    }
#undef ISSUE
}

// ---------------------------------------------------------------------------
extern "C" void kernel_launch(void* const* d_in, const int* in_sizes, int n_in,
                              void* d_out, int out_size) {
    const float* x  = (const float*)d_in[0];   // [4096, 256]
    const float* cp = (const float*)d_in[1];   // [256, 256, 19]
    const float* sc = (const float*)d_in[2];   // [256, 256]
    float* out = (float*)d_out;                // [4096, 256]

    cudaFuncSetAttribute(kan_mma, cudaFuncAttributeMaxDynamicSharedMemorySize,
                         SMTOT);

    prep_a<<<BATCH,   IN_DIM>>>(x);
    prep_b<<<OUT_DIM, IN_DIM>>>(cp, sc);
    kan_mma<<<256, 256, SMTOT>>>(out);
}

// round 13
// speedup vs baseline: 1.6741x; 1.2139x over previous
#include <cuda_runtime.h>
#include <cuda_bf16.h>
#include <math.h>
#include <stdint.h>

#define IN_DIM   256
#define OUT_DIM  256
#define BATCH    4096
#define NROWS    12
#define KSEG     (IN_DIM * NROWS)      // 3072 dense K per term
#define KA       (2 * KSEG)            // A_cat row: hi | lo           = 6144
#define KB       (3 * KSEG)            // B_cat row: Whi | Wlo | Whi   = 9216
#define KC       192                   // K per chunk
#define NCH      (KB / KC)             // 48
#define CSEG     (KSEG / KC)           // 16

// Scratch (static __device__ — no allocation).
__device__ __nv_bfloat16 g_A[(size_t)BATCH * KA];    // ~50 MB (L2-resident)
__device__ __nv_bfloat16 g_B[(size_t)OUT_DIM * KB];  // ~4.7 MB

// ===========================================================================
// Kernel 1: A_cat — dense 12-wide basis/silu per (b,i), split hi|lo bf16.
// Smem-staged: pack 12+12 bf16 into u32 pairs, then coalesced uint4 stores.
// ===========================================================================
__global__ void __launch_bounds__(256) prep_a(const float* __restrict__ x) {
    __shared__ uint32_t st[3072];                 // 12 KB row image for batch b
    int b = blockIdx.x;
    int i = threadIdx.x;
    float xv = x[(size_t)b * IN_DIM + i];
    float t8 = xv * 8.0f;
    float fl = floorf(t8);
    float u  = t8 - fl;
    int k0l = min(max((int)fl, 0), 7);
    const float inv6 = 1.0f / 6.0f;
    float u2 = u * u, u3 = u2 * u;
    float omu = 1.0f - u;
    float d[NROWS];
#pragma unroll
    for (int kk = 0; kk < NROWS; kk++) d[kk] = 0.0f;
    d[k0l + 0] = omu * omu * omu * inv6;
    d[k0l + 1] = (3.0f * u3 - 6.0f * u2 + 4.0f) * inv6;
    d[k0l + 2] = (-3.0f * u3 + 3.0f * u2 + 3.0f * u + 1.0f) * inv6;
    d[k0l + 3] = u3 * inv6;
    d[11]      = xv / (1.0f + __expf(-xv));       // silu (fast exp; err ~2^-17)

    unsigned short hb[NROWS], lb[NROWS];
#pragma unroll
    for (int kk = 0; kk < NROWS; kk++) {
        float v = d[kk];
        __nv_bfloat16 h = __float2bfloat16(v);
        float lo = v - __bfloat162float(h);
        __nv_bfloat16 l = __float2bfloat16(lo);
        hb[kk] = *reinterpret_cast<unsigned short*>(&h);
        lb[kk] = *reinterpret_cast<unsigned short*>(&l);
    }
#pragma unroll
    for (int j = 0; j < 6; j++) {
        st[i * 6 + j]        = (uint32_t)hb[2 * j] | ((uint32_t)hb[2 * j + 1] << 16);
        st[1536 + i * 6 + j] = (uint32_t)lb[2 * j] | ((uint32_t)lb[2 * j + 1] << 16);
    }
    __syncthreads();

    const uint4* s4 = reinterpret_cast<const uint4*>(st);
    uint4* g4 = reinterpret_cast<uint4*>(g_A) + (size_t)b * 768;
#pragma unroll
    for (int p = 0; p < 3; p++)
        g4[p * 256 + i] = s4[p * 256 + i];
}

// ===========================================================================
// Kernel 2: B_cat — W[i][kk][o] = sc*cp (row 11 = sc), split Whi|Wlo|Whi.
// ===========================================================================
__global__ void prep_b(const float* __restrict__ cp, const float* __restrict__ sc) {
    int o = blockIdx.x;
    int i = threadIdx.x;
    float s = sc[i * OUT_DIM + o];
    const float* cpp = cp + (size_t)(i * OUT_DIM + o) * 19;
    __nv_bfloat16* pb = g_B + (size_t)o * KB + i * NROWS;
#pragma unroll
    for (int kk = 0; kk < NROWS; kk++) {
        float w = (kk < 11) ? s * cpp[kk + 8] : s;
        __nv_bfloat16 h = __float2bfloat16(w);
        float lo = w - __bfloat162float(h);
        pb[kk]            = h;
        pb[KSEG + kk]     = __float2bfloat16(lo);
        pb[2 * KSEG + kk] = h;
    }
}

// ===========================================================================
// PTX helpers (sm_80-class only: cp.async, ldmatrix, mma.sync — no tcgen05)
// ===========================================================================
__device__ __forceinline__ uint32_t smem_u32(const void* p) {
    uint32_t a;
    asm("{ .reg .u64 t; cvta.to.shared.u64 t, %1; cvt.u32.u64 %0, t; }"
        : "=r"(a) : "l"(p));
    return a;
}
__device__ __forceinline__ void cp16(uint32_t dst, const void* src) {
    asm volatile("cp.async.cg.shared.global [%0], [%1], 16;"
                 :: "r"(dst), "l"(src) : "memory");
}
__device__ __forceinline__ void cp_commit() {
    asm volatile("cp.async.commit_group;" ::: "memory");
}
template <int N>
__device__ __forceinline__ void cp_wait() {
    asm volatile("cp.async.wait_group %0;" :: "n"(N) : "memory");
}
__device__ __forceinline__ void ldm_x4(uint32_t* r, uint32_t addr) {
    asm volatile("ldmatrix.sync.aligned.m8n8.x4.shared.b16 {%0,%1,%2,%3}, [%4];"
                 : "=r"(r[0]), "=r"(r[1]), "=r"(r[2]), "=r"(r[3]) : "r"(addr));
}
__device__ __forceinline__ void mma16816(float* d, const uint32_t* a,
                                         const uint32_t* b) {
    asm volatile(
        "mma.sync.aligned.m16n8k16.row.col.f32.bf16.bf16.f32 "
        "{%0,%1,%2,%3}, {%4,%5,%6,%7}, {%8,%9}, {%0,%1,%2,%3};"
        : "+f"(d[0]), "+f"(d[1]), "+f"(d[2]), "+f"(d[3])
        : "r"(a[0]), "r"(a[1]), "r"(a[2]), "r"(a[3]), "r"(b[0]), "r"(b[1]));
}

// ===========================================================================
// Kernel 3: HMMA GEMM. out[4096,256] = A_cat · B_cat^T.
// CTA: M=128, N=64. grid = 32 btiles x 4 ntiles = 128 CTAs, 256 threads.
// Warps 4(M)x2(N); warp tile 32x32.
// KC=192 (12 k-steps per barrier), 3-stage cp.async, ONE sync/chunk,
// fragment double-buffering across k-steps (LDSM of ks+1 overlaps MMAs of ks).
// Smem rows 400B stride (r*400 mod 128 = r*16 -> conflict-free ldmatrix).
// ===========================================================================
#define ROWB  400                       // bytes per padded smem row (384 data)
#define ASTG  (128 * ROWB)              // 51200
#define BSTG  (64 * ROWB)               // 25600
#define STG_B (ASTG + BSTG)             // 76800 per stage
#define SMTOT (3 * STG_B)               // 230400 (fits 227KB opt-in)

__global__ void __launch_bounds__(256) kan_mma(float* __restrict__ out) {
    extern __shared__ char smem[];
    uint32_t sbase = smem_u32(smem);
    uint32_t sA[3], sB[3];
#pragma unroll
    for (int s = 0; s < 3; s++) {
        sA[s] = sbase + s * STG_B;
        sB[s] = sbase + s * STG_B + ASTG;
    }

    int tid  = threadIdx.x;
    int wid  = tid >> 5;
    int lane = tid & 31;
    int btile = blockIdx.x >> 2;          // 0..31
    int ntile = blockIdx.x & 3;           // 0..3
    int warp_m = wid >> 1;                // 0..3
    int warp_n = wid & 1;                 // 0..1

    // ---- cp.async per-thread mapping ----
    // row block = tid>>3 (0..31), unit u0 = tid&7 (of 24 16B-units per 384B row)
    // A: 12 ops  (j/3 -> +32 rows, j%3 -> +8 units); B: 6 ops (rows<64)
    int r0 = tid >> 3;
    int u0 = tid & 7;
    const __nv_bfloat16* gAb =
        g_A + (size_t)(btile * 128 + r0) * KA + u0 * 8;
    const __nv_bfloat16* gBb =
        g_B + (size_t)(ntile * 64 + r0) * KB + u0 * 8;
    uint32_t dAb = r0 * ROWB + u0 * 16;

    // ---- ldmatrix per-lane base offsets (R9 geometry) ----
    uint32_t a_off[2];
#pragma unroll
    for (int mt = 0; mt < 2; mt++) {
        int r = warp_m * 32 + mt * 16 + (lane & 7) + 8 * ((lane >> 3) & 1);
        a_off[mt] = r * ROWB + (lane >> 4) * 16;
    }
    uint32_t b_off[2];
#pragma unroll
    for (int np = 0; np < 2; np++) {
        int r = warp_n * 32 + np * 16 + ((lane >> 4) & 1) * 8 + (lane & 7);
        b_off[np] = r * ROWB + ((lane >> 3) & 1) * 16;
    }

    float acc[2][4][4];
#pragma unroll
    for (int mt = 0; mt < 2; mt++)
#pragma unroll
        for (int nt = 0; nt < 4; nt++)
#pragma unroll
            for (int q = 0; q < 4; q++) acc[mt][nt][q] = 0.0f;

#define ISSUE(c, s) do {                                                        \
        int _c = (c);                                                           \
        int _seg = _c / CSEG;                                                   \
        int _aoff = ((_seg == 2) ? KSEG : 0) + (_c - _seg * CSEG) * KC;         \
        int _boff = _c * KC;                                                    \
        _Pragma("unroll")                                                       \
        for (int j = 0; j < 12; j++)                                            \
            cp16(sA[s] + dAb + (j / 3) * (32 * ROWB) + (j % 3) * 128,           \
                 gAb + _aoff + (size_t)(j / 3) * (32 * KA) + (j % 3) * 64);     \
        _Pragma("unroll")                                                       \
        for (int j = 0; j < 6; j++)                                             \
            cp16(sB[s] + dAb + (j / 3) * (32 * ROWB) + (j % 3) * 128,           \
                 gBb + _boff + (size_t)(j / 3) * (32 * KB) + (j % 3) * 64);     \
        cp_commit();                                                            \
    } while (0)

#define LOADF(buf, s, ks) do {                                                  \
        uint32_t _kb = (ks) * 32;                                               \
        _Pragma("unroll")                                                       \
        for (int mt = 0; mt < 2; mt++)                                          \
            ldm_x4(afr[buf][mt], sA[s] + a_off[mt] + _kb);                      \
        _Pragma("unroll")                                                       \
        for (int np = 0; np < 2; np++)                                          \
            ldm_x4(bfr[buf][np], sB[s] + b_off[np] + _kb);                      \
    } while (0)

#define MMAS(buf) do {                                                          \
        _Pragma("unroll")                                                       \
        for (int mt = 0; mt < 2; mt++) {                                        \
            _Pragma("unroll")                                                   \
            for (int nt = 0; nt < 4; nt++) {                                    \
                uint32_t bb[2] = { bfr[buf][nt >> 1][(nt & 1) * 2 + 0],         \
                                   bfr[buf][nt >> 1][(nt & 1) * 2 + 1] };       \
                mma16816(acc[mt][nt], afr[buf][mt], bb);                        \
            }                                                                   \
        }                                                                       \
    } while (0)

    // prologue: 2 chunks in flight
    ISSUE(0, 0);
    ISSUE(1, 1);

    for (int c = 0; c < NCH; c++) {
        int s = c % 3;
        if (c + 1 < NCH) cp_wait<1>(); else cp_wait<0>();
        __syncthreads();

        if (c + 2 < NCH) ISSUE(c + 2, (c + 2) % 3);   // stage freed at iter c-1

        uint32_t afr[2][2][4], bfr[2][2][4];
        LOADF(0, s, 0);
#pragma unroll
        for (int ks = 0; ks < 12; ks++) {
            if (ks < 11) LOADF((ks + 1) & 1, s, ks + 1);
            MMAS(ks & 1);
        }
    }

    // ---- epilogue ----
    int mg = btile * 128 + warp_m * 32 + (lane >> 2);
    int ng = ntile * 64 + warp_n * 32 + (lane & 3) * 2;
#pragma unroll
    for (int mt = 0; mt < 2; mt++) {
#pragma unroll
        for (int nt = 0; nt < 4; nt++) {
            int m0 = mg + mt * 16;
            int n0 = ng + nt * 8;
            float2 v0 = make_float2(acc[mt][nt][0], acc[mt][nt][1]);
            float2 v1 = make_float2(acc[mt][nt][2], acc[mt][nt][3]);
            *reinterpret_cast<float2*>(out + (size_t)m0 * OUT_DIM + n0) = v0;
            *reinterpret_cast<float2*>(out + (size_t)(m0 + 8) * OUT_DIM + n0) = v1;
        }
    }
#undef MMAS
#undef LOADF
#undef ISSUE
}

// ---------------------------------------------------------------------------
extern "C" void kernel_launch(void* const* d_in, const int* in_sizes, int n_in,
                              void* d_out, int out_size) {
    const float* x  = (const float*)d_in[0];   // [4096, 256]
    const float* cp = (const float*)d_in[1];   // [256, 256, 19]
    const float* sc = (const float*)d_in[2];   // [256, 256]
    float* out = (float*)d_out;                // [4096, 256]

    cudaFuncSetAttribute(kan_mma, cudaFuncAttributeMaxDynamicSharedMemorySize,
                         SMTOT);

    prep_a<<<BATCH,   IN_DIM>>>(x);
    prep_b<<<OUT_DIM, IN_DIM>>>(cp, sc);
    kan_mma<<<128, 256, SMTOT>>>(out);
}